// round 1
// baseline (speedup 1.0000x reference)
#include <cuda_runtime.h>
#include <math_constants.h>
#include <cstdint>

#define BB 8
#define SS_ 1024
#define D0 128
#define DD 256
#define HH 8
#define HD 32
#define BH (BB*HH)     // 64
#define BSr (BB*SS_)   // 8192

// ---------------- scratch (device globals: no allocation allowed) ----------
__device__ float g_Q[BH*SS_*HD];      // [(b*H+h)*S + s]*HD + d
__device__ float g_K[BH*SS_*HD];
__device__ float g_V[BH*SS_*HD];
__device__ float g_maskadd[BH*SS_];   // 0.0f or -inf per (b,h,key)
__device__ float g_AO[BSr*DD];        // pre-Wo context, [bs][e]

// ---------------- packed f32x2 helpers -------------------------------------
__device__ __forceinline__ unsigned long long f2pack(float lo, float hi) {
    unsigned long long r;
    asm("mov.b64 %0, {%1, %2};" : "=l"(r) : "f"(lo), "f"(hi));
    return r;
}
__device__ __forceinline__ void ffma2(unsigned long long& d,
                                      unsigned long long a,
                                      unsigned long long b) {
    asm("fma.rn.f32x2 %0, %1, %2, %0;" : "+l"(d) : "l"(a), "l"(b));
}
__device__ __forceinline__ float f2sum(unsigned long long v) {
    float lo, hi;
    asm("mov.b64 {%0, %1}, %2;" : "=f"(lo), "=f"(hi) : "l"(v));
    return lo + hi;
}

// ---------------- K1: tiled GEMM  C[32 x 64] = A[32 x Kd] * W[64 x Kd]^T ----
// A row-major [M][Kd], W row-major [N][Kd].
// dest: 0->g_Q, 1->g_K, 2->g_V (head-scatter), 3-> Oarg direct [row*ldo + e]
// A==nullptr means A = g_AO (for the output projection).
#define GK_CH 128
__global__ __launch_bounds__(256)
void gemm32x64(const float* __restrict__ A, const float* __restrict__ W,
               float* __restrict__ Oarg, int Kd, int dest, int ldo)
{
    extern __shared__ float sm[];
    float* Xs = sm;                    // 32*128 floats
    float* Wt = sm + 32 * GK_CH;       // 128*65 floats (transposed W chunk)

    const float* Ap = A ? A : g_AO;
    const int tid = threadIdx.x;
    const int w = tid >> 5, lane = tid & 31;
    const int row0 = blockIdx.x * 32;
    const int n0 = blockIdx.y * 64;

    unsigned long long acc[4][2];
#pragma unroll
    for (int r = 0; r < 4; r++)
#pragma unroll
        for (int c = 0; c < 2; c++) acc[r][c] = 0ull;

    for (int k0 = 0; k0 < Kd; k0 += GK_CH) {
        // stage A tile (coalesced)
        for (int idx = tid; idx < 32 * GK_CH; idx += 256) {
            int r = idx >> 7, d = idx & 127;
            Xs[r * GK_CH + d] = Ap[(size_t)(row0 + r) * Kd + k0 + d];
        }
        // stage W^T tile: Wt[d][e], pad 65 -> conflict-free
        for (int idx = tid; idx < 64 * GK_CH; idx += 256) {
            int e = idx >> 7, d = idx & 127;
            Wt[d * 65 + e] = W[(size_t)(n0 + e) * Kd + k0 + d];
        }
        __syncthreads();
#pragma unroll 16
        for (int j = 0; j < GK_CH / 2; j++) {
            unsigned long long qa[4];
#pragma unroll
            for (int r = 0; r < 4; r++)
                qa[r] = *reinterpret_cast<const unsigned long long*>(
                            &Xs[(4 * w + r) * GK_CH + 2 * j]);
#pragma unroll
            for (int c = 0; c < 2; c++) {
                unsigned long long b2 = f2pack(Wt[(2 * j) * 65 + lane + 32 * c],
                                               Wt[(2 * j + 1) * 65 + lane + 32 * c]);
#pragma unroll
                for (int r = 0; r < 4; r++) ffma2(acc[r][c], qa[r], b2);
            }
        }
        __syncthreads();
    }

    float* Ohead = (dest == 0) ? g_Q : (dest == 1) ? g_K : g_V;
#pragma unroll
    for (int r = 0; r < 4; r++) {
        int rowg = row0 + 4 * w + r;
#pragma unroll
        for (int c = 0; c < 2; c++) {
            float y = f2sum(acc[r][c]);
            int e = n0 + lane + 32 * c;
            if (dest < 3) {
                int b = rowg >> 10, s = rowg & 1023;
                int h = e >> 5, d = e & 31;
                Ohead[(((size_t)(b * HH + h)) * SS_ + s) * HD + d] = y;
            } else {
                Oarg[(size_t)rowg * ldo + e] = y;
            }
        }
    }
}

// ---------------- K2: mask from Q row sums ---------------------------------
__global__ __launch_bounds__(256)
void qsum_kernel()
{
    int row = blockIdx.x * 256 + threadIdx.x;   // [0, BH*S)
    const float4* p = reinterpret_cast<const float4*>(g_Q + (size_t)row * HD);
    float s = 0.f;
#pragma unroll
    for (int i = 0; i < 8; i++) {
        float4 v = p[i];
        s += ((v.x + v.y) + (v.z + v.w));
    }
    g_maskadd[row] = (s != 0.0f) ? 0.0f : -CUDART_INF_F;
}

// ---------------- K3: fused attention --------------------------------------
// grid (S/32, BH), 256 threads. Per CTA: 32 queries x all 1024 keys.
// Warp w owns query rows 4w..4w+3 end-to-end (max/exp/sum/AV), so softmax
// needs only intra-warp sync; only K/V tile staging uses __syncthreads.
__global__ __launch_bounds__(256)
void attn_kernel(const float* __restrict__ U, float* __restrict__ attnp,
                 int has_attn)
{
    extern __shared__ float sm[];
    float* Qs  = sm;                    // 32*32      = 1024 f
    float* msk = sm + 1024;             // 1024 f
    float* KVt = sm + 2048;             // 32*129     = 4128 f (K^T / V^T tile)
    float* Ss  = sm + 2048 + 4128;      // 32*1024    = 32768 f (scores/probs)

    const int tid = threadIdx.x, w = tid >> 5, lane = tid & 31;
    const int bh = blockIdx.y;
    const int q0 = blockIdx.x * 32;
    const float inv_scale = 0.17677669529663687f;   // 1/sqrt(32)

    const float* gq = g_Q + (size_t)bh * SS_ * HD;
    const float* gk = g_K + (size_t)bh * SS_ * HD;
    const float* gv = g_V + (size_t)bh * SS_ * HD;

    // stage Q tile + mask
    for (int idx = tid; idx < 32 * HD; idx += 256)
        Qs[idx] = gq[(size_t)q0 * HD + idx];
    for (int k = tid; k < SS_; k += 256)
        msk[k] = g_maskadd[bh * SS_ + k];
    __syncthreads();

    float lmax[4] = {-CUDART_INF_F, -CUDART_INF_F, -CUDART_INF_F, -CUDART_INF_F};
    const size_t urow = ((size_t)bh * SS_ + q0) * SS_;

    // ---- phase 1: scores = (Q K^T + U)/sqrt(hd) + maskadd -> Ss ----
    for (int kb = 0; kb < SS_; kb += 128) {
        __syncthreads();
        for (int idx = tid; idx < 128 * HD; idx += 256) {
            int k = idx >> 5, d = idx & 31;
            KVt[d * 129 + k] = gk[(size_t)(kb + k) * HD + d];
        }
        __syncthreads();

        float ureg[4][4];
#pragma unroll
        for (int r = 0; r < 4; r++) {
            const float* up = U + urow + (size_t)(4 * w + r) * SS_ + kb + lane;
#pragma unroll
            for (int c = 0; c < 4; c++) ureg[r][c] = up[32 * c];
        }

        unsigned long long acc[4][4];
#pragma unroll
        for (int r = 0; r < 4; r++)
#pragma unroll
            for (int c = 0; c < 4; c++) acc[r][c] = 0ull;

#pragma unroll
        for (int j = 0; j < HD / 2; j++) {
            unsigned long long qa[4];
#pragma unroll
            for (int r = 0; r < 4; r++)
                qa[r] = *reinterpret_cast<const unsigned long long*>(
                            &Qs[(4 * w + r) * HD + 2 * j]);
#pragma unroll
            for (int c = 0; c < 4; c++) {
                unsigned long long b2 = f2pack(KVt[(2 * j) * 129 + lane + 32 * c],
                                               KVt[(2 * j + 1) * 129 + lane + 32 * c]);
#pragma unroll
                for (int r = 0; r < 4; r++) ffma2(acc[r][c], qa[r], b2);
            }
        }
#pragma unroll
        for (int r = 0; r < 4; r++)
#pragma unroll
            for (int c = 0; c < 4; c++) {
                int kk = kb + lane + 32 * c;
                float s = (f2sum(acc[r][c]) + ureg[r][c]) * inv_scale + msk[kk];
                lmax[r] = fmaxf(lmax[r], s);
                Ss[(4 * w + r) * SS_ + kk] = s;
            }
    }

    // ---- phase 2: softmax (warp-local, rows 4w..4w+3) ----
#pragma unroll
    for (int r = 0; r < 4; r++)
#pragma unroll
        for (int off = 16; off; off >>= 1)
            lmax[r] = fmaxf(lmax[r], __shfl_xor_sync(0xffffffffu, lmax[r], off));
    __syncwarp();

    float rsum[4];
#pragma unroll
    for (int r = 0; r < 4; r++) {
        float* row = Ss + (4 * w + r) * SS_;
        float m = lmax[r];
        float lsum = 0.f;
#pragma unroll
        for (int j = 0; j < 8; j++) {
            float4 v = *reinterpret_cast<float4*>(&row[4 * lane + 128 * j]);
            v.x = __expf(v.x - m); v.y = __expf(v.y - m);
            v.z = __expf(v.z - m); v.w = __expf(v.w - m);
            *reinterpret_cast<float4*>(&row[4 * lane + 128 * j]) = v;
            lsum += (v.x + v.y) + (v.z + v.w);
        }
#pragma unroll
        for (int off = 16; off; off >>= 1)
            lsum += __shfl_xor_sync(0xffffffffu, lsum, off);
        rsum[r] = lsum;
    }
    __syncwarp();

#pragma unroll
    for (int r = 0; r < 4; r++) {
        float inv = 1.0f / rsum[r];
        float* row = Ss + (4 * w + r) * SS_;
        float4* gout = has_attn
            ? reinterpret_cast<float4*>(attnp + ((size_t)bh * SS_ + q0 + 4 * w + r) * SS_)
            : nullptr;
#pragma unroll
        for (int j = 0; j < 8; j++) {
            float4 v = *reinterpret_cast<float4*>(&row[4 * lane + 128 * j]);
            v.x *= inv; v.y *= inv; v.z *= inv; v.w *= inv;
            *reinterpret_cast<float4*>(&row[4 * lane + 128 * j]) = v;
            if (has_attn) gout[lane + 32 * j] = v;
        }
    }
    __syncwarp();

    // ---- phase 3: out = attn @ V  (lane = head dim) ----
    unsigned long long oacc[4] = {0ull, 0ull, 0ull, 0ull};
    for (int vb = 0; vb < SS_; vb += 128) {
        __syncthreads();
        for (int idx = tid; idx < 128 * HD; idx += 256) {
            int k = idx >> 5, d = idx & 31;
            KVt[d * 129 + k] = gv[(size_t)(vb + k) * HD + d];
        }
        __syncthreads();
        const float* vrow = KVt + lane * 129;
#pragma unroll 16
        for (int k = 0; k < 128; k += 2) {
            unsigned long long v2 = f2pack(vrow[k], vrow[k + 1]);
#pragma unroll
            for (int r = 0; r < 4; r++) {
                unsigned long long p2 = *reinterpret_cast<const unsigned long long*>(
                        &Ss[(4 * w + r) * SS_ + vb + k]);
                ffma2(oacc[r], p2, v2);
            }
        }
    }
    {
        int b = bh >> 3, h = bh & 7;
#pragma unroll
        for (int r = 0; r < 4; r++) {
            int s = q0 + 4 * w + r;
            g_AO[((size_t)b * SS_ + s) * DD + h * HD + lane] = f2sum(oacc[r]);
        }
    }
}

// ---------------- launcher --------------------------------------------------
extern "C" void kernel_launch(void* const* d_in, const int* in_sizes, int n_in,
                              void* d_out, int out_size)
{
    const float* query = (const float*)d_in[0];
    const float* U     = (const float*)d_in[1];
    const float* Wq    = (const float*)d_in[2];
    const float* Wk    = (const float*)d_in[3];
    const float* Wv    = (const float*)d_in[4];
    const float* Wo    = (const float*)d_in[5];

    float* outp = (float*)d_out;
    const long long total = (long long)BSr * D0 + (long long)BH * SS_ * SS_;
    float* attnp = nullptr;
    int has_attn = 0;
    if ((long long)out_size >= total) { attnp = outp + (size_t)BSr * D0; has_attn = 1; }

    const size_t gemm_smem = (size_t)(32 * GK_CH + GK_CH * 65) * sizeof(float); // 49664 B
    const size_t attn_smem = (size_t)(1024 + 1024 + 32 * 129 + 32 * 1024) * sizeof(float); // 155776 B
    cudaFuncSetAttribute(gemm32x64, cudaFuncAttributeMaxDynamicSharedMemorySize, (int)gemm_smem);
    cudaFuncSetAttribute(attn_kernel, cudaFuncAttributeMaxDynamicSharedMemorySize, (int)attn_smem);

    // Q/K/V projections: M=8192, N=256, Kd=128
    dim3 pg(BSr / 32, 4);
    gemm32x64<<<pg, 256, gemm_smem>>>(query, Wq, nullptr, D0, 0, 0);
    gemm32x64<<<pg, 256, gemm_smem>>>(query, Wk, nullptr, D0, 1, 0);
    gemm32x64<<<pg, 256, gemm_smem>>>(query, Wv, nullptr, D0, 2, 0);

    // mask
    qsum_kernel<<<BH * SS_ / 256, 256>>>();

    // attention
    attn_kernel<<<dim3(SS_ / 32, BH), 256, attn_smem>>>(U, attnp, has_attn);

    // output projection: M=8192, N=128, Kd=256, A = g_AO
    gemm32x64<<<dim3(BSr / 32, 2), 256, gemm_smem>>>(nullptr, Wo, outp, DD, 3, D0);
}

// round 2
// speedup vs baseline: 1.7824x; 1.7824x over previous
#include <cuda_runtime.h>
#include <math_constants.h>
#include <cstdint>

#define BB 8
#define SS_ 1024
#define D0 128
#define DD 256
#define HH 8
#define HD 32
#define BH (BB*HH)     // 64
#define BSr (BB*SS_)   // 8192
#define LOG2E 1.4426950408889634f

// ---------------- scratch (device globals: no allocation allowed) ----------
__device__ float g_Q[BH*SS_*HD];      // [(b*H+h)*S + s]*HD + d
__device__ float g_K[BH*SS_*HD];
__device__ float g_V[BH*SS_*HD];
__device__ float g_maskadd[BH*SS_];   // 0.0f or -inf per (b,h,key)
__device__ float g_AO[BSr*DD];        // pre-Wo context, [bs][e]
__device__ float g_SF[(size_t)BH*SS_*SS_]; // fallback score buffer (unused when attn output exists)

// ---------------- packed f32x2 helpers -------------------------------------
__device__ __forceinline__ unsigned long long f2pack(float lo, float hi) {
    unsigned long long r;
    asm("mov.b64 %0, {%1, %2};" : "=l"(r) : "f"(lo), "f"(hi));
    return r;
}
__device__ __forceinline__ void ffma2(unsigned long long& d,
                                      unsigned long long a,
                                      unsigned long long b) {
    asm("fma.rn.f32x2 %0, %1, %2, %0;" : "+l"(d) : "l"(a), "l"(b));
}
__device__ __forceinline__ float f2sum(unsigned long long v) {
    float lo, hi;
    asm("mov.b64 {%0, %1}, %2;" : "=f"(lo), "=f"(hi) : "l"(v));
    return lo + hi;
}

// ---------------- K1: tiled GEMM  C[32 x 64] = A[32 x Kd] * W[64 x Kd]^T ----
#define GK_CH 128
__global__ __launch_bounds__(256)
void gemm32x64(const float* __restrict__ A, const float* __restrict__ W,
               float* __restrict__ Oarg, int Kd, int dest, int ldo)
{
    extern __shared__ float sm[];
    float* Xs = sm;                    // 32*128 floats
    float* Wt = sm + 32 * GK_CH;       // 128*65 floats (transposed W chunk)

    const float* Ap = A ? A : g_AO;
    const int tid = threadIdx.x;
    const int w = tid >> 5, lane = tid & 31;
    const int row0 = blockIdx.x * 32;
    const int n0 = blockIdx.y * 64;

    unsigned long long acc[4][2];
#pragma unroll
    for (int r = 0; r < 4; r++)
#pragma unroll
        for (int c = 0; c < 2; c++) acc[r][c] = 0ull;

    for (int k0 = 0; k0 < Kd; k0 += GK_CH) {
        for (int idx = tid; idx < 32 * GK_CH; idx += 256) {
            int r = idx >> 7, d = idx & 127;
            Xs[r * GK_CH + d] = Ap[(size_t)(row0 + r) * Kd + k0 + d];
        }
        for (int idx = tid; idx < 64 * GK_CH; idx += 256) {
            int e = idx >> 7, d = idx & 127;
            Wt[d * 65 + e] = W[(size_t)(n0 + e) * Kd + k0 + d];
        }
        __syncthreads();
#pragma unroll 16
        for (int j = 0; j < GK_CH / 2; j++) {
            unsigned long long qa[4];
#pragma unroll
            for (int r = 0; r < 4; r++)
                qa[r] = *reinterpret_cast<const unsigned long long*>(
                            &Xs[(4 * w + r) * GK_CH + 2 * j]);
#pragma unroll
            for (int c = 0; c < 2; c++) {
                unsigned long long b2 = f2pack(Wt[(2 * j) * 65 + lane + 32 * c],
                                               Wt[(2 * j + 1) * 65 + lane + 32 * c]);
#pragma unroll
                for (int r = 0; r < 4; r++) ffma2(acc[r][c], qa[r], b2);
            }
        }
        __syncthreads();
    }

    float* Ohead = (dest == 0) ? g_Q : (dest == 1) ? g_K : g_V;
#pragma unroll
    for (int r = 0; r < 4; r++) {
        int rowg = row0 + 4 * w + r;
#pragma unroll
        for (int c = 0; c < 2; c++) {
            float y = f2sum(acc[r][c]);
            int e = n0 + lane + 32 * c;
            if (dest < 3) {
                int b = rowg >> 10, s = rowg & 1023;
                int h = e >> 5, d = e & 31;
                Ohead[(((size_t)(b * HH + h)) * SS_ + s) * HD + d] = y;
            } else {
                Oarg[(size_t)rowg * ldo + e] = y;
            }
        }
    }
}

// ---------------- K2: mask from Q row sums ---------------------------------
__global__ __launch_bounds__(256)
void qsum_kernel()
{
    int row = blockIdx.x * 256 + threadIdx.x;   // [0, BH*S)
    const float4* p = reinterpret_cast<const float4*>(g_Q + (size_t)row * HD);
    float s = 0.f;
#pragma unroll
    for (int i = 0; i < 8; i++) {
        float4 v = p[i];
        s += ((v.x + v.y) + (v.z + v.w));
    }
    g_maskadd[row] = (s != 0.0f) ? 0.0f : -CUDART_INF_F;
}

// ---------------- K3: fused attention (register scores + online softmax) ----
// grid (S/32, BH), 256 threads, 3 CTAs/SM. Warp w owns rows 4w..4w+3.
// Phase 1: scores in regs -> raw s to gmem (attn buffer, stays in L2),
//          per-lane online (m,l).
// Phase 2: warp-merge (m,l) -> c_r = m*log2e + log2(l).
// Phase 3: reload s (L2 hit), p = exp2(s*log2e - c_r) -> attn (final) + smem
//          P-tile; AV from smem with f32x2.
__global__ __launch_bounds__(256, 3)
void attn_kernel(const float* __restrict__ U, float* __restrict__ sattn)
{
    extern __shared__ float sm[];
    float* Qs  = sm;                    // 32*32 = 1024
    float* msk = sm + 1024;             // 1024
    float* cst = sm + 2048;             // 32 (+32 pad)
    float* KV  = sm + 2112;             // K: 128*34=4352 | Vt: 32*130=4160
    float* Ps  = sm + 2112 + 4352;      // 32*132 = 4224
    // total 10688 floats = 42752 B

    const int tid = threadIdx.x, w = tid >> 5, lane = tid & 31;
    const int bh = blockIdx.y;
    const int q0 = blockIdx.x * 32;
    const float inv_scale = 0.17677669529663687f;   // 1/sqrt(32)

    const float* gq = g_Q + (size_t)bh * SS_ * HD;
    const float* gk = g_K + (size_t)bh * SS_ * HD;
    const float* gv = g_V + (size_t)bh * SS_ * HD;
    float* srow = sattn + ((size_t)bh * SS_ + q0) * SS_;   // this CTA's 32x1024 slab

    // stage Q tile + mask
    {
        const float4* q4 = reinterpret_cast<const float4*>(gq + (size_t)q0 * HD);
        reinterpret_cast<float4*>(Qs)[tid] = q4[tid];                  // 256 x16B = 4KB
        const float4* m4 = reinterpret_cast<const float4*>(g_maskadd + bh * SS_);
        reinterpret_cast<float4*>(msk)[tid] = m4[tid];                 // 4KB
    }

    float m_loc[4], l_loc[4];
#pragma unroll
    for (int r = 0; r < 4; r++) { m_loc[r] = -CUDART_INF_F; l_loc[r] = 0.f; }

    // ---- phase 1 ----
    for (int kb = 0; kb < SS_; kb += 128) {
        __syncthreads();
        // stage K tile [k][d], row pad 34 (8B-aligned rows, direct LDS.64 pairs)
        {
            const float4* src = reinterpret_cast<const float4*>(gk + (size_t)kb * HD);
#pragma unroll
            for (int t = 0; t < 4; t++) {
                int i = tid + t * 256;
                float4 v = src[i];
                int k = i >> 3, dg = (i & 7) << 2;
                float* dst = &KV[k * 34 + dg];
                *reinterpret_cast<float2*>(dst)     = make_float2(v.x, v.y);
                *reinterpret_cast<float2*>(dst + 2) = make_float2(v.z, v.w);
            }
        }
        __syncthreads();

        unsigned long long acc[4][4];
#pragma unroll
        for (int r = 0; r < 4; r++)
#pragma unroll
            for (int c = 0; c < 4; c++) acc[r][c] = 0ull;

#pragma unroll
        for (int j = 0; j < HD / 2; j++) {
            unsigned long long qa[4];
#pragma unroll
            for (int r = 0; r < 4; r++)
                qa[r] = *reinterpret_cast<const unsigned long long*>(
                            &Qs[(4 * w + r) * HD + 2 * j]);
#pragma unroll
            for (int c = 0; c < 4; c++) {
                unsigned long long b2 = *reinterpret_cast<const unsigned long long*>(
                            &KV[(lane + 32 * c) * 34 + 2 * j]);
#pragma unroll
                for (int r = 0; r < 4; r++) ffma2(acc[r][c], qa[r], b2);
            }
        }

        // epilogue: s = (qk + U)*scale + mask; stream raw s; online (m,l)
#pragma unroll
        for (int r = 0; r < 4; r++) {
            const float* up = U + ((size_t)bh * SS_ + q0 + 4 * w + r) * SS_ + kb + lane;
            float* sp = srow + (size_t)(4 * w + r) * SS_ + kb + lane;
            float s[4];
            float bm = -CUDART_INF_F;
#pragma unroll
            for (int c = 0; c < 4; c++) {
                s[c] = (f2sum(acc[r][c]) + up[32 * c]) * inv_scale + msk[kb + lane + 32 * c];
                sp[32 * c] = s[c];
                bm = fmaxf(bm, s[c]);
            }
            float nm = fmaxf(m_loc[r], bm);
            float lr = l_loc[r] * exp2f((m_loc[r] - nm) * LOG2E);
#pragma unroll
            for (int c = 0; c < 4; c++) lr += exp2f((s[c] - nm) * LOG2E);
            l_loc[r] = lr;
            m_loc[r] = nm;
        }
    }

    // ---- phase 2: warp-merge (m,l), fold to c_r ----
#pragma unroll
    for (int r = 0; r < 4; r++) {
        float m = m_loc[r], l = l_loc[r];
#pragma unroll
        for (int off = 16; off; off >>= 1) {
            float mo = __shfl_xor_sync(0xffffffffu, m, off);
            float lo = __shfl_xor_sync(0xffffffffu, l, off);
            float nm = fmaxf(m, mo);
            l = l * exp2f((m - nm) * LOG2E) + lo * exp2f((mo - nm) * LOG2E);
            m = nm;
        }
        if (lane == 0) cst[4 * w + r] = m * LOG2E + __log2f(l);
    }

    // ---- phase 3: normalize + write attn + AV ----
    unsigned long long oacc[4] = {0ull, 0ull, 0ull, 0ull};
    for (int vb = 0; vb < SS_; vb += 128) {
        __syncthreads();   // cst visible on first iter; KV/Ps reuse-safe after
        // stage Vt [d][k], row pad 130
        {
            const float4* src = reinterpret_cast<const float4*>(gv + (size_t)vb * HD);
#pragma unroll
            for (int t = 0; t < 4; t++) {
                int i = tid + t * 256;
                float4 v = src[i];
                int k = i >> 3, dg = (i & 7) << 2;
                KV[(dg + 0) * 130 + k] = v.x;
                KV[(dg + 1) * 130 + k] = v.y;
                KV[(dg + 2) * 130 + k] = v.z;
                KV[(dg + 3) * 130 + k] = v.w;
            }
        }
        // stage P tile: reload raw s (L2), p = exp2(s*L - c_r), write back + smem
        {
            int row = tid >> 3, cb = (tid & 7) << 4;
            float c_r = cst[row];
            float4* sp4 = reinterpret_cast<float4*>(srow + (size_t)row * SS_ + vb + cb);
            float4* ps4 = reinterpret_cast<float4*>(&Ps[row * 132 + cb]);
#pragma unroll
            for (int i = 0; i < 4; i++) {
                float4 v = sp4[i];
                v.x = exp2f(v.x * LOG2E - c_r);
                v.y = exp2f(v.y * LOG2E - c_r);
                v.z = exp2f(v.z * LOG2E - c_r);
                v.w = exp2f(v.w * LOG2E - c_r);
                sp4[i] = v;     // final attn out
                ps4[i] = v;     // smem tile for AV
            }
        }
        __syncthreads();
        // AV: lane = head dim d
#pragma unroll 8
        for (int k = 0; k < 128; k += 2) {
            unsigned long long v2 = *reinterpret_cast<const unsigned long long*>(
                    &KV[lane * 130 + k]);
#pragma unroll
            for (int r = 0; r < 4; r++) {
                unsigned long long p2 = *reinterpret_cast<const unsigned long long*>(
                        &Ps[(4 * w + r) * 132 + k]);
                ffma2(oacc[r], p2, v2);
            }
        }
    }

    {
        int b = bh >> 3, h = bh & 7;
#pragma unroll
        for (int r = 0; r < 4; r++) {
            int s = q0 + 4 * w + r;
            g_AO[((size_t)b * SS_ + s) * DD + h * HD + lane] = f2sum(oacc[r]);
        }
    }
}

// ---------------- launcher --------------------------------------------------
extern "C" void kernel_launch(void* const* d_in, const int* in_sizes, int n_in,
                              void* d_out, int out_size)
{
    const float* query = (const float*)d_in[0];
    const float* U     = (const float*)d_in[1];
    const float* Wq    = (const float*)d_in[2];
    const float* Wk    = (const float*)d_in[3];
    const float* Wv    = (const float*)d_in[4];
    const float* Wo    = (const float*)d_in[5];

    float* outp = (float*)d_out;
    const long long total = (long long)BSr * D0 + (long long)BH * SS_ * SS_;
    float* attnp = nullptr;
    if ((long long)out_size >= total) attnp = outp + (size_t)BSr * D0;

    float* sbuf = attnp;
    if (!sbuf) { cudaGetSymbolAddress((void**)&sbuf, g_SF); }  // fallback scratch

    const size_t gemm_smem = (size_t)(32 * GK_CH + GK_CH * 65) * sizeof(float); // 49664 B
    const size_t attn_smem = (size_t)(1024 + 1024 + 64 + 128 * 34 + 32 * 132) * sizeof(float); // 42752 B
    cudaFuncSetAttribute(gemm32x64, cudaFuncAttributeMaxDynamicSharedMemorySize, (int)gemm_smem);
    cudaFuncSetAttribute(attn_kernel, cudaFuncAttributeMaxDynamicSharedMemorySize, (int)attn_smem);

    // Q/K/V projections: M=8192, N=256, Kd=128
    dim3 pg(BSr / 32, 4);
    gemm32x64<<<pg, 256, gemm_smem>>>(query, Wq, nullptr, D0, 0, 0);
    gemm32x64<<<pg, 256, gemm_smem>>>(query, Wk, nullptr, D0, 1, 0);
    gemm32x64<<<pg, 256, gemm_smem>>>(query, Wv, nullptr, D0, 2, 0);

    // mask
    qsum_kernel<<<BH * SS_ / 256, 256>>>();

    // attention (scores round-trip through the attn output buffer)
    attn_kernel<<<dim3(SS_ / 32, BH), 256, attn_smem>>>(U, sbuf);

    // output projection: M=8192, N=128, Kd=256, A = g_AO
    gemm32x64<<<dim3(BSr / 32, 2), 256, gemm_smem>>>(nullptr, Wo, outp, DD, 3, D0);
}

// round 4
// speedup vs baseline: 1.9248x; 1.0799x over previous
#include <cuda_runtime.h>
#include <math_constants.h>
#include <cstdint>

#define BB 8
#define SS_ 1024
#define D0 128
#define DD 256
#define HH 8
#define HD 32
#define BH (BB*HH)     // 64
#define BSr (BB*SS_)   // 8192
#define LOG2E 1.4426950408889634f

// ---------------- scratch (device globals: no allocation allowed) ----------
__device__ float g_Q[BH*SS_*HD];      // [(b*H+h)*S + s]*HD + d
__device__ float g_K[BH*SS_*HD];
__device__ float g_V[BH*SS_*HD];
__device__ float g_maskadd[BH*SS_];   // 0.0f or -inf per (b,h,key)
__device__ float g_AO[BSr*DD];        // pre-Wo context, [bs][e]
__device__ float g_SF[(size_t)BH*SS_*SS_]; // fallback score buffer

// ---------------- packed f32x2 helpers -------------------------------------
__device__ __forceinline__ unsigned long long f2pack(float lo, float hi) {
    unsigned long long r;
    asm("mov.b64 %0, {%1, %2};" : "=l"(r) : "f"(lo), "f"(hi));
    return r;
}
__device__ __forceinline__ void ffma2(unsigned long long& d,
                                      unsigned long long a,
                                      unsigned long long b) {
    asm("fma.rn.f32x2 %0, %1, %2, %0;" : "+l"(d) : "l"(a), "l"(b));
}
__device__ __forceinline__ float f2sum(unsigned long long v) {
    float lo, hi;
    asm("mov.b64 {%0, %1}, %2;" : "=f"(lo), "=f"(hi) : "l"(v));
    return lo + hi;
}
__device__ __forceinline__ float ex2(float x) {
    float r;
    asm("ex2.approx.ftz.f32 %0, %1;" : "=f"(r) : "f"(x));
    return r;
}

// ---------------- K1: fused Q/K/V projection GEMM + mask --------------------
// grid (BSr/32, 4, 3): z selects {Wq->g_Q(+mask), Wk->g_K, Wv->g_V}.
// C[32 x 64] = A[32 x 128] * W[64 x 128]^T, head-scattered store.
__global__ __launch_bounds__(256)
void gemmQKV(const float* __restrict__ A,
             const float* __restrict__ Wq, const float* __restrict__ Wk,
             const float* __restrict__ Wv)
{
    extern __shared__ float sm[];
    float* Xs = sm;                 // 32*128
    float* Wt = sm + 32 * 128;      // 128*65

    const int tid = threadIdx.x;
    const int w = tid >> 5, lane = tid & 31;
    const int row0 = blockIdx.x * 32;
    const int n0 = blockIdx.y * 64;
    const int z = blockIdx.z;
    const float* W = (z == 0) ? Wq : (z == 1) ? Wk : Wv;
    float* Ohead = (z == 0) ? g_Q : (z == 1) ? g_K : g_V;

    for (int idx = tid; idx < 32 * 128; idx += 256) {
        int r = idx >> 7, d = idx & 127;
        Xs[r * 128 + d] = A[(size_t)(row0 + r) * D0 + d];
    }
    for (int idx = tid; idx < 64 * 128; idx += 256) {
        int e = idx >> 7, d = idx & 127;
        Wt[d * 65 + e] = W[(size_t)(n0 + e) * D0 + d];
    }
    __syncthreads();

    unsigned long long acc[4][2];
#pragma unroll
    for (int r = 0; r < 4; r++)
#pragma unroll
        for (int c = 0; c < 2; c++) acc[r][c] = 0ull;

#pragma unroll 16
    for (int j = 0; j < 64; j++) {
        unsigned long long qa[4];
#pragma unroll
        for (int r = 0; r < 4; r++)
            qa[r] = *reinterpret_cast<const unsigned long long*>(
                        &Xs[(4 * w + r) * 128 + 2 * j]);
#pragma unroll
        for (int c = 0; c < 2; c++) {
            unsigned long long b2 = f2pack(Wt[(2 * j) * 65 + lane + 32 * c],
                                           Wt[(2 * j + 1) * 65 + lane + 32 * c]);
#pragma unroll
            for (int r = 0; r < 4; r++) ffma2(acc[r][c], qa[r], b2);
        }
    }

#pragma unroll
    for (int r = 0; r < 4; r++) {
        int rowg = row0 + 4 * w + r;
        int b = rowg >> 10, s = rowg & 1023;
#pragma unroll
        for (int c = 0; c < 2; c++) {
            float y = f2sum(acc[r][c]);
            int e = n0 + lane + 32 * c;
            int h = e >> 5, d = e & 31;
            Ohead[(((size_t)(b * HH + h)) * SS_ + s) * HD + d] = y;
            if (z == 0) {   // fused mask: head row-sum (all 32 d live in this warp)
                float hs = y;
#pragma unroll
                for (int off = 16; off; off >>= 1)
                    hs += __shfl_xor_sync(0xffffffffu, hs, off);
                if (lane == 0)
                    g_maskadd[(b * HH + h) * SS_ + s] = (hs != 0.0f) ? 0.0f : -CUDART_INF_F;
            }
        }
    }
}

// ---------------- K2: output projection  out[8192x128] = g_AO[8192x256] Wo^T
__global__ __launch_bounds__(256)
void gemmO(const float* __restrict__ W, float* __restrict__ Oarg)
{
    extern __shared__ float sm[];
    float* Xs = sm;                 // 32*128
    float* Wt = sm + 32 * 128;      // 128*65

    const int tid = threadIdx.x;
    const int w = tid >> 5, lane = tid & 31;
    const int row0 = blockIdx.x * 32;
    const int n0 = blockIdx.y * 64;

    unsigned long long acc[4][2];
#pragma unroll
    for (int r = 0; r < 4; r++)
#pragma unroll
        for (int c = 0; c < 2; c++) acc[r][c] = 0ull;

    for (int k0 = 0; k0 < DD; k0 += 128) {
        __syncthreads();
        for (int idx = tid; idx < 32 * 128; idx += 256) {
            int r = idx >> 7, d = idx & 127;
            Xs[r * 128 + d] = g_AO[(size_t)(row0 + r) * DD + k0 + d];
        }
        for (int idx = tid; idx < 64 * 128; idx += 256) {
            int e = idx >> 7, d = idx & 127;
            Wt[d * 65 + e] = W[(size_t)(n0 + e) * DD + k0 + d];
        }
        __syncthreads();
#pragma unroll 16
        for (int j = 0; j < 64; j++) {
            unsigned long long qa[4];
#pragma unroll
            for (int r = 0; r < 4; r++)
                qa[r] = *reinterpret_cast<const unsigned long long*>(
                            &Xs[(4 * w + r) * 128 + 2 * j]);
#pragma unroll
            for (int c = 0; c < 2; c++) {
                unsigned long long b2 = f2pack(Wt[(2 * j) * 65 + lane + 32 * c],
                                               Wt[(2 * j + 1) * 65 + lane + 32 * c]);
#pragma unroll
                for (int r = 0; r < 4; r++) ffma2(acc[r][c], qa[r], b2);
            }
        }
    }
#pragma unroll
    for (int r = 0; r < 4; r++)
#pragma unroll
        for (int c = 0; c < 2; c++)
            Oarg[(size_t)(row0 + 4 * w + r) * D0 + n0 + lane + 32 * c] = f2sum(acc[r][c]);
}

// ---------------- K3: fused attention (no-max softmax, single exp sweep) ----
// grid (S/32, BH), 256 threads, 3 CTAs/SM. Warp w owns rows 4w..4w+3.
// Phase 1: s -> e = exp2(s*log2e) streamed to gmem (stays L2-hot); l += e.
// Phase 2: warp-sum l -> inv = 1/l.
// Phase 3: reload e, p = e*inv -> final attn + smem P tile; AV with f32x2.
__global__ __launch_bounds__(256, 3)
void attn_kernel(const float* __restrict__ U, float* __restrict__ sattn)
{
    extern __shared__ float sm[];
    float* Qs  = sm;                    // 32*32 = 1024
    float* msk = sm + 1024;             // 1024
    float* cst = sm + 2048;             // 32 (+32 pad)
    float* KV  = sm + 2112;             // K: 128*34=4352 | Vt: 32*130=4160
    float* Ps  = sm + 2112 + 4352;      // 32*132 = 4224
    // total 10688 floats = 42752 B

    const int tid = threadIdx.x, w = tid >> 5, lane = tid & 31;
    const int bh = blockIdx.y;
    const int q0 = blockIdx.x * 32;
    const float inv_scale = 0.17677669529663687f;   // 1/sqrt(32)

    const float* gq = g_Q + (size_t)bh * SS_ * HD;
    const float* gk = g_K + (size_t)bh * SS_ * HD;
    const float* gv = g_V + (size_t)bh * SS_ * HD;
    float* srow = sattn + ((size_t)bh * SS_ + q0) * SS_;

    {
        const float4* q4 = reinterpret_cast<const float4*>(gq + (size_t)q0 * HD);
        reinterpret_cast<float4*>(Qs)[tid] = q4[tid];
        const float4* m4 = reinterpret_cast<const float4*>(g_maskadd + bh * SS_);
        reinterpret_cast<float4*>(msk)[tid] = m4[tid];
    }

    float l_loc[4] = {0.f, 0.f, 0.f, 0.f};

    // ---- phase 1: e = exp(score) -> gmem; accumulate l ----
    for (int kb = 0; kb < SS_; kb += 128) {
        __syncthreads();
        {   // stage K tile [k][d], pad 34
            const float4* src = reinterpret_cast<const float4*>(gk + (size_t)kb * HD);
#pragma unroll
            for (int t = 0; t < 4; t++) {
                int i = tid + t * 256;
                float4 v = src[i];
                int k = i >> 3, dg = (i & 7) << 2;
                float* dst = &KV[k * 34 + dg];
                *reinterpret_cast<float2*>(dst)     = make_float2(v.x, v.y);
                *reinterpret_cast<float2*>(dst + 2) = make_float2(v.z, v.w);
            }
        }
        __syncthreads();

        unsigned long long acc[4][4];
#pragma unroll
        for (int r = 0; r < 4; r++)
#pragma unroll
            for (int c = 0; c < 4; c++) acc[r][c] = 0ull;

#pragma unroll
        for (int j = 0; j < HD / 2; j++) {
            unsigned long long qa[4];
#pragma unroll
            for (int r = 0; r < 4; r++)
                qa[r] = *reinterpret_cast<const unsigned long long*>(
                            &Qs[(4 * w + r) * HD + 2 * j]);
#pragma unroll
            for (int c = 0; c < 4; c++) {
                unsigned long long b2 = *reinterpret_cast<const unsigned long long*>(
                            &KV[(lane + 32 * c) * 34 + 2 * j]);
#pragma unroll
                for (int r = 0; r < 4; r++) ffma2(acc[r][c], qa[r], b2);
            }
        }

#pragma unroll
        for (int r = 0; r < 4; r++) {
            const float* up = U + ((size_t)bh * SS_ + q0 + 4 * w + r) * SS_ + kb + lane;
            float* ep = srow + (size_t)(4 * w + r) * SS_ + kb + lane;
            float lr = l_loc[r];
#pragma unroll
            for (int c = 0; c < 4; c++) {
                float s = (f2sum(acc[r][c]) + up[32 * c]) * inv_scale
                        + msk[kb + lane + 32 * c];
                float e = ex2(s * LOG2E);     // exp(s); -inf -> 0
                ep[32 * c] = e;
                lr += e;
            }
            l_loc[r] = lr;
        }
    }

    // ---- phase 2: warp-sum l -> inv ----
#pragma unroll
    for (int r = 0; r < 4; r++) {
        float l = l_loc[r];
#pragma unroll
        for (int off = 16; off; off >>= 1)
            l += __shfl_xor_sync(0xffffffffu, l, off);
        if (lane == 0) cst[4 * w + r] = 1.0f / l;
    }

    // ---- phase 3: normalize + write attn + AV ----
    unsigned long long oacc[4] = {0ull, 0ull, 0ull, 0ull};
    for (int vb = 0; vb < SS_; vb += 128) {
        __syncthreads();   // cst visible on first iter; KV/Ps reuse-safe after
        {   // stage Vt [d][k], pad 130
            const float4* src = reinterpret_cast<const float4*>(gv + (size_t)vb * HD);
#pragma unroll
            for (int t = 0; t < 4; t++) {
                int i = tid + t * 256;
                float4 v = src[i];
                int k = i >> 3, dg = (i & 7) << 2;
                KV[(dg + 0) * 130 + k] = v.x;
                KV[(dg + 1) * 130 + k] = v.y;
                KV[(dg + 2) * 130 + k] = v.z;
                KV[(dg + 3) * 130 + k] = v.w;
            }
        }
        {   // P tile: p = e * inv -> final attn + smem
            int row = tid >> 3, cb = (tid & 7) << 4;
            float inv = cst[row];
            float4* ep4 = reinterpret_cast<float4*>(srow + (size_t)row * SS_ + vb + cb);
            float4* ps4 = reinterpret_cast<float4*>(&Ps[row * 132 + cb]);
#pragma unroll
            for (int i = 0; i < 4; i++) {
                float4 v = ep4[i];
                v.x *= inv; v.y *= inv; v.z *= inv; v.w *= inv;
                ep4[i] = v;     // final attn out
                ps4[i] = v;     // smem tile for AV
            }
        }
        __syncthreads();
        // AV: lane = head dim d
#pragma unroll 4
        for (int k = 0; k < 128; k += 4) {
            unsigned long long v2a = *reinterpret_cast<const unsigned long long*>(
                    &KV[lane * 130 + k]);
            unsigned long long v2b = *reinterpret_cast<const unsigned long long*>(
                    &KV[lane * 130 + k + 2]);
#pragma unroll
            for (int r = 0; r < 4; r++) {
                float4 p4 = *reinterpret_cast<const float4*>(&Ps[(4 * w + r) * 132 + k]);
                ffma2(oacc[r], f2pack(p4.x, p4.y), v2a);
                ffma2(oacc[r], f2pack(p4.z, p4.w), v2b);
            }
        }
    }

    {
        int b = bh >> 3, h = bh & 7;
#pragma unroll
        for (int r = 0; r < 4; r++) {
            int s = q0 + 4 * w + r;
            g_AO[((size_t)b * SS_ + s) * DD + h * HD + lane] = f2sum(oacc[r]);
        }
    }
}

// ---------------- launcher --------------------------------------------------
extern "C" void kernel_launch(void* const* d_in, const int* in_sizes, int n_in,
                              void* d_out, int out_size)
{
    const float* query = (const float*)d_in[0];
    const float* U     = (const float*)d_in[1];
    const float* Wq    = (const float*)d_in[2];
    const float* Wk    = (const float*)d_in[3];
    const float* Wv    = (const float*)d_in[4];
    const float* Wo    = (const float*)d_in[5];

    float* outp = (float*)d_out;
    const long long total = (long long)BSr * D0 + (long long)BH * SS_ * SS_;
    float* attnp = nullptr;
    if ((long long)out_size >= total) attnp = outp + (size_t)BSr * D0;

    float* sbuf = attnp;
    if (!sbuf) { cudaGetSymbolAddress((void**)&sbuf, g_SF); }

    const size_t gemm_smem = (size_t)(32 * 128 + 128 * 65) * sizeof(float); // 49664 B
    const size_t attn_smem = (size_t)(1024 + 1024 + 64 + 128 * 34 + 32 * 132) * sizeof(float); // 42752 B
    cudaFuncSetAttribute(gemmQKV, cudaFuncAttributeMaxDynamicSharedMemorySize, (int)gemm_smem);
    cudaFuncSetAttribute(gemmO, cudaFuncAttributeMaxDynamicSharedMemorySize, (int)gemm_smem);
    cudaFuncSetAttribute(attn_kernel, cudaFuncAttributeMaxDynamicSharedMemorySize, (int)attn_smem);

    // Q/K/V projections (+ fused mask): M=8192, N=256, Kd=128, z = which W
    gemmQKV<<<dim3(BSr / 32, 4, 3), 256, gemm_smem>>>(query, Wq, Wk, Wv);

    // attention (exp'd scores round-trip through the attn output buffer)
    attn_kernel<<<dim3(SS_ / 32, BH), 256, attn_smem>>>(U, sbuf);

    // output projection: M=8192, N=128, Kd=256
    gemmO<<<dim3(BSr / 32, 2), 256, gemm_smem>>>(Wo, outp);
}

// round 5
// speedup vs baseline: 2.1941x; 1.1399x over previous
#include <cuda_runtime.h>
#include <math_constants.h>
#include <cstdint>

#define BB 8
#define SS_ 1024
#define D0 128
#define DD 256
#define HH 8
#define HD 32
#define BH (BB*HH)     // 64
#define BSr (BB*SS_)   // 8192
#define LOG2E 1.4426950408889634f

// ---------------- scratch ---------------------------------------------------
__device__ float g_Q [BH*SS_*HD];          // [bh][s][d]
__device__ float g_Kt[BH*HD*SS_];          // [bh][d][s]  (transposed)
__device__ float g_Vt[BH*HD*SS_];          // [bh][d][s]  (transposed)
__device__ float g_maskadd[BH*SS_];        // 0 or -inf per (bh, key)
__device__ float g_AO[BSr*DD];             // pre-Wo context [bs][e]
__device__ float g_SF[(size_t)BH*SS_*SS_]; // fallback score buffer

// ---------------- packed f32x2 helpers -------------------------------------
__device__ __forceinline__ unsigned long long f2pack(float lo, float hi) {
    unsigned long long r;
    asm("mov.b64 %0, {%1, %2};" : "=l"(r) : "f"(lo), "f"(hi));
    return r;
}
__device__ __forceinline__ void ffma2(unsigned long long& d,
                                      unsigned long long a,
                                      unsigned long long b) {
    asm("fma.rn.f32x2 %0, %1, %2, %0;" : "+l"(d) : "l"(a), "l"(b));
}
__device__ __forceinline__ float f2sum(unsigned long long v) {
    float lo, hi;
    asm("mov.b64 {%0, %1}, %2;" : "=f"(lo), "=f"(hi) : "l"(v));
    return lo + hi;
}
__device__ __forceinline__ float ex2(float x) {
    float r;
    asm("ex2.approx.ftz.f32 %0, %1;" : "=f"(r) : "f"(x));
    return r;
}

// ---------------- K1: fused Q/K/V projection (+mask, +K/V transpose) --------
// grid (BSr/64, 4, 3). C[64 x 64] = A[64 x 128] * W[64 x 128]^T.
// z=0 -> g_Q (normal layout) + maskadd; z=1 -> g_Kt; z=2 -> g_Vt (transposed).
__global__ __launch_bounds__(256, 2)
void gemmQKV(const float* __restrict__ A,
             const float* __restrict__ Wq, const float* __restrict__ Wk,
             const float* __restrict__ Wv)
{
    extern __shared__ float sm[];
    float* Xs = sm;                 // 64*128 = 8192 (reused as Cs 64x65 later)
    float* Wt = sm + 8192;          // 128*65 = 8320

    const int tid = threadIdx.x;
    const int w = tid >> 5, lane = tid & 31;
    const int r0 = w * 8;
    const int row0 = blockIdx.x * 64;
    const int n0 = blockIdx.y * 64;
    const int z = blockIdx.z;
    const float* W = (z == 0) ? Wq : (z == 1) ? Wk : Wv;

    for (int idx = tid; idx < 64 * 128; idx += 256) {
        int r = idx >> 7, d = idx & 127;
        Xs[r * 128 + d] = A[(size_t)(row0 + r) * D0 + d];
    }
    for (int idx = tid; idx < 64 * 128; idx += 256) {
        int e = idx >> 7, d = idx & 127;
        Wt[d * 65 + e] = W[(size_t)(n0 + e) * D0 + d];
    }
    __syncthreads();

    unsigned long long acc[8][2];
#pragma unroll
    for (int r = 0; r < 8; r++)
#pragma unroll
        for (int c = 0; c < 2; c++) acc[r][c] = 0ull;

#pragma unroll 8
    for (int j = 0; j < 64; j++) {
        unsigned long long qa[8];
#pragma unroll
        for (int r = 0; r < 8; r++)
            qa[r] = *reinterpret_cast<const unsigned long long*>(
                        &Xs[(r0 + r) * 128 + 2 * j]);
#pragma unroll
        for (int c = 0; c < 2; c++) {
            unsigned long long b2 = f2pack(Wt[(2 * j) * 65 + lane + 32 * c],
                                           Wt[(2 * j + 1) * 65 + lane + 32 * c]);
#pragma unroll
            for (int r = 0; r < 8; r++) ffma2(acc[r][c], qa[r], b2);
        }
    }

    if (z == 0) {
        int b = row0 >> 10;
#pragma unroll
        for (int r = 0; r < 8; r++) {
            int s = (row0 + r0 + r) & 1023;
#pragma unroll
            for (int c = 0; c < 2; c++) {
                float y = f2sum(acc[r][c]);
                int e = n0 + lane + 32 * c;
                int h = e >> 5, d = e & 31;
                g_Q[(((size_t)(b * HH + h)) * SS_ + s) * HD + d] = y;
                float hs = y;   // head row-sum for mask (one head per c-group)
#pragma unroll
                for (int off = 16; off; off >>= 1)
                    hs += __shfl_xor_sync(0xffffffffu, hs, off);
                if (lane == 0)
                    g_maskadd[(b * HH + h) * SS_ + s] = (hs != 0.0f) ? 0.0f : -CUDART_INF_F;
            }
        }
    } else {
        // stage C into smem, then write transposed coalesced
        __syncthreads();
        float* Cs = Xs;   // 64 x 65
#pragma unroll
        for (int r = 0; r < 8; r++)
#pragma unroll
            for (int c = 0; c < 2; c++)
                Cs[(r0 + r) * 65 + lane + 32 * c] = f2sum(acc[r][c]);
        __syncthreads();
        float* gT = (z == 1) ? g_Kt : g_Vt;
        int b = row0 >> 10;
#pragma unroll
        for (int t = 0; t < 4; t++) {
            int i = tid + t * 256;          // < 1024
            int e = i >> 4, sq = i & 15;
            float4 v = make_float4(Cs[(4 * sq + 0) * 65 + e],
                                   Cs[(4 * sq + 1) * 65 + e],
                                   Cs[(4 * sq + 2) * 65 + e],
                                   Cs[(4 * sq + 3) * 65 + e]);
            int eg = n0 + e;
            int h = eg >> 5, d = eg & 31;
            *reinterpret_cast<float4*>(
                &gT[(((size_t)(b * HH + h)) * HD + d) * SS_ + (row0 & 1023) + 4 * sq]) = v;
        }
    }
}

// ---------------- K2: output projection  out = g_AO[8192x256] * Wo^T --------
__global__ __launch_bounds__(256, 2)
void gemmO(const float* __restrict__ W, float* __restrict__ Oarg)
{
    extern __shared__ float sm[];
    float* Xs = sm;                 // 64*128
    float* Wt = sm + 8192;          // 128*65

    const int tid = threadIdx.x;
    const int w = tid >> 5, lane = tid & 31;
    const int r0 = w * 8;
    const int row0 = blockIdx.x * 64;
    const int n0 = blockIdx.y * 64;

    unsigned long long acc[8][2];
#pragma unroll
    for (int r = 0; r < 8; r++)
#pragma unroll
        for (int c = 0; c < 2; c++) acc[r][c] = 0ull;

    for (int k0 = 0; k0 < DD; k0 += 128) {
        __syncthreads();
        for (int idx = tid; idx < 64 * 128; idx += 256) {
            int r = idx >> 7, d = idx & 127;
            Xs[r * 128 + d] = g_AO[(size_t)(row0 + r) * DD + k0 + d];
        }
        for (int idx = tid; idx < 64 * 128; idx += 256) {
            int e = idx >> 7, d = idx & 127;
            Wt[d * 65 + e] = W[(size_t)(n0 + e) * DD + k0 + d];
        }
        __syncthreads();
#pragma unroll 8
        for (int j = 0; j < 64; j++) {
            unsigned long long qa[8];
#pragma unroll
            for (int r = 0; r < 8; r++)
                qa[r] = *reinterpret_cast<const unsigned long long*>(
                            &Xs[(r0 + r) * 128 + 2 * j]);
#pragma unroll
            for (int c = 0; c < 2; c++) {
                unsigned long long b2 = f2pack(Wt[(2 * j) * 65 + lane + 32 * c],
                                               Wt[(2 * j + 1) * 65 + lane + 32 * c]);
#pragma unroll
                for (int r = 0; r < 8; r++) ffma2(acc[r][c], qa[r], b2);
            }
        }
    }
#pragma unroll
    for (int r = 0; r < 8; r++)
#pragma unroll
        for (int c = 0; c < 2; c++)
            Oarg[(size_t)(row0 + r0 + r) * D0 + n0 + lane + 32 * c] = f2sum(acc[r][c]);
}

// ---------------- K3: fused attention ---------------------------------------
// grid (S/64, BH), 256 thr, 2 CTAs/SM. Warp w owns rows 8w..8w+7.
// Phase 1: QK from Kt tile -> e = exp(score) to gmem; l += e.
// Phase 2: warp-sum l -> inv.
// Phase 3: reload e (L2), p = e*inv -> attn + Ps; AV from Vt tile.
__global__ __launch_bounds__(256, 2)
void attn_kernel(const float* __restrict__ U, float* __restrict__ sattn)
{
    extern __shared__ float sm[];
    float* Qs    = sm;              // 64*32  = 2048
    float* msk   = sm + 2048;       // 1024
    float* inv_s = sm + 3072;       // 64 (+pad to 3152)
    float* KVt   = sm + 3152;       // K tile [32][132]=4224 | V tile [32][130]=4160
    float* Ps    = sm + 3152 + 4224;// 64*132 = 8448
    // total 15824 floats = 63296 B

    const int tid = threadIdx.x, w = tid >> 5, lane = tid & 31;
    const int r0 = w * 8;
    const int bh = blockIdx.y;
    const int q0 = blockIdx.x * 64;
    const float inv_scale = 0.17677669529663687f;   // 1/sqrt(32)

    const float* gq  = g_Q  + (size_t)bh * SS_ * HD;
    const float* gkt = g_Kt + (size_t)bh * HD * SS_;
    const float* gvt = g_Vt + (size_t)bh * HD * SS_;
    float* srow = sattn + ((size_t)bh * SS_ + q0) * SS_;

    {   // stage Q tile (64x32) + mask
        const float4* q4 = reinterpret_cast<const float4*>(gq + (size_t)q0 * HD);
        reinterpret_cast<float4*>(Qs)[tid]       = q4[tid];
        reinterpret_cast<float4*>(Qs)[tid + 256] = q4[tid + 256];
        const float4* m4 = reinterpret_cast<const float4*>(g_maskadd + bh * SS_);
        reinterpret_cast<float4*>(msk)[tid] = m4[tid];
    }

    float l_loc[8];
#pragma unroll
    for (int r = 0; r < 8; r++) l_loc[r] = 0.f;

    // ---- phase 1 ----
    for (int kb = 0; kb < SS_; kb += 128) {
        __syncthreads();
        {   // stage K tile [d][k] pad 132 from g_Kt (coalesced LDG.128 -> STS.128)
#pragma unroll
            for (int t = 0; t < 4; t++) {
                int i = tid + t * 256;      // < 1024
                int d = i >> 5, kq = i & 31;
                float4 v = *reinterpret_cast<const float4*>(
                               &gkt[(size_t)d * SS_ + kb + 4 * kq]);
                *reinterpret_cast<float4*>(&KVt[d * 132 + 4 * kq]) = v;
            }
        }
        __syncthreads();

        unsigned long long acc[8][4];
#pragma unroll
        for (int r = 0; r < 8; r++)
#pragma unroll
            for (int c = 0; c < 4; c++) acc[r][c] = 0ull;

#pragma unroll
        for (int j = 0; j < HD / 2; j++) {
            unsigned long long qa[8];
#pragma unroll
            for (int r = 0; r < 8; r++)
                qa[r] = *reinterpret_cast<const unsigned long long*>(
                            &Qs[(r0 + r) * HD + 2 * j]);
#pragma unroll
            for (int c = 0; c < 4; c++) {
                unsigned long long b2 = f2pack(KVt[(2 * j) * 132 + lane + 32 * c],
                                               KVt[(2 * j + 1) * 132 + lane + 32 * c]);
#pragma unroll
                for (int r = 0; r < 8; r++) ffma2(acc[r][c], qa[r], b2);
            }
        }

#pragma unroll
        for (int r = 0; r < 8; r++) {
            const float* up = U + ((size_t)bh * SS_ + q0 + r0 + r) * SS_ + kb + lane;
            float* ep = srow + (size_t)(r0 + r) * SS_ + kb + lane;
            float lr = l_loc[r];
#pragma unroll
            for (int c = 0; c < 4; c++) {
                float s = (f2sum(acc[r][c]) + up[32 * c]) * inv_scale
                        + msk[kb + lane + 32 * c];
                float e = ex2(s * LOG2E);   // exp(s); -inf -> 0
                ep[32 * c] = e;
                lr += e;
            }
            l_loc[r] = lr;
        }
    }

    // ---- phase 2: warp-sum l -> inv ----
#pragma unroll
    for (int r = 0; r < 8; r++) {
        float l = l_loc[r];
#pragma unroll
        for (int off = 16; off; off >>= 1)
            l += __shfl_xor_sync(0xffffffffu, l, off);
        if (lane == 0) inv_s[r0 + r] = 1.0f / l;
    }

    // ---- phase 3: normalize + write attn + AV ----
    unsigned long long oacc[8];
#pragma unroll
    for (int r = 0; r < 8; r++) oacc[r] = 0ull;

    for (int vb = 0; vb < SS_; vb += 128) {
        __syncthreads();    // inv visible (1st iter); KVt/Ps reuse-safe after
        {   // stage V tile [d][k] pad 130 (STS.64 pair, row-reads conflict-free)
#pragma unroll
            for (int t = 0; t < 4; t++) {
                int i = tid + t * 256;
                int d = i >> 5, kq = i & 31;
                float4 v = *reinterpret_cast<const float4*>(
                               &gvt[(size_t)d * SS_ + vb + 4 * kq]);
                float* dst = &KVt[d * 130 + 4 * kq];
                *reinterpret_cast<float2*>(dst)     = make_float2(v.x, v.y);
                *reinterpret_cast<float2*>(dst + 2) = make_float2(v.z, v.w);
            }
        }
        {   // P tile: p = e * inv -> final attn + Ps
#pragma unroll
            for (int t = 0; t < 8; t++) {
                int i = tid + t * 256;      // < 2048
                int row = i >> 5, q4 = i & 31;
                float iv = inv_s[row];
                float4* ep4 = reinterpret_cast<float4*>(
                                  srow + (size_t)row * SS_ + vb + 4 * q4);
                float4 v = *ep4;
                v.x *= iv; v.y *= iv; v.z *= iv; v.w *= iv;
                *ep4 = v;
                *reinterpret_cast<float4*>(&Ps[row * 132 + 4 * q4]) = v;
            }
        }
        __syncthreads();
        // AV: lane = head dim d
#pragma unroll 4
        for (int k = 0; k < 128; k += 4) {
            unsigned long long v2a = *reinterpret_cast<const unsigned long long*>(
                    &KVt[lane * 130 + k]);
            unsigned long long v2b = *reinterpret_cast<const unsigned long long*>(
                    &KVt[lane * 130 + k + 2]);
#pragma unroll
            for (int r = 0; r < 8; r++) {
                float4 p4 = *reinterpret_cast<const float4*>(&Ps[(r0 + r) * 132 + k]);
                ffma2(oacc[r], f2pack(p4.x, p4.y), v2a);
                ffma2(oacc[r], f2pack(p4.z, p4.w), v2b);
            }
        }
    }

    {
        int b = bh >> 3, h = bh & 7;
#pragma unroll
        for (int r = 0; r < 8; r++) {
            int s = q0 + r0 + r;
            g_AO[((size_t)b * SS_ + s) * DD + h * HD + lane] = f2sum(oacc[r]);
        }
    }
}

// ---------------- launcher --------------------------------------------------
extern "C" void kernel_launch(void* const* d_in, const int* in_sizes, int n_in,
                              void* d_out, int out_size)
{
    const float* query = (const float*)d_in[0];
    const float* U     = (const float*)d_in[1];
    const float* Wq    = (const float*)d_in[2];
    const float* Wk    = (const float*)d_in[3];
    const float* Wv    = (const float*)d_in[4];
    const float* Wo    = (const float*)d_in[5];

    float* outp = (float*)d_out;
    const long long total = (long long)BSr * D0 + (long long)BH * SS_ * SS_;
    float* attnp = nullptr;
    if ((long long)out_size >= total) attnp = outp + (size_t)BSr * D0;

    float* sbuf = attnp;
    if (!sbuf) { cudaGetSymbolAddress((void**)&sbuf, g_SF); }

    const size_t gemm_smem = (size_t)(64 * 128 + 128 * 65) * sizeof(float);   // 66048 B
    const size_t attn_smem = (size_t)15824 * sizeof(float);                   // 63296 B
    cudaFuncSetAttribute(gemmQKV, cudaFuncAttributeMaxDynamicSharedMemorySize, (int)gemm_smem);
    cudaFuncSetAttribute(gemmO, cudaFuncAttributeMaxDynamicSharedMemorySize, (int)gemm_smem);
    cudaFuncSetAttribute(attn_kernel, cudaFuncAttributeMaxDynamicSharedMemorySize, (int)attn_smem);

    // Q/K/V projections (+mask, +K/V transpose): M=8192, N=256
    gemmQKV<<<dim3(BSr / 64, 4, 3), 256, gemm_smem>>>(query, Wq, Wk, Wv);

    // attention
    attn_kernel<<<dim3(SS_ / 64, BH), 256, attn_smem>>>(U, sbuf);

    // output projection
    gemmO<<<dim3(BSr / 64, 2), 256, gemm_smem>>>(Wo, outp);
}

// round 7
// speedup vs baseline: 2.2865x; 1.0421x over previous
#include <cuda_runtime.h>
#include <math_constants.h>
#include <cstdint>

#define BB 8
#define SS_ 1024
#define D0 128
#define DD 256
#define HH 8
#define HD 32
#define BH (BB*HH)     // 64
#define BSr (BB*SS_)   // 8192
#define LOG2E 1.4426950408889634f

// ---------------- scratch ---------------------------------------------------
__device__ float g_Q [BH*SS_*HD];          // [bh][s][d]
__device__ float g_Kp[BH*HD*SS_];          // paired: [bh][d/2][s] float2
__device__ float g_Vt[BH*HD*SS_];          // [bh][d][s]
__device__ float g_maskadd[BH*SS_];        // 0 or -inf per (bh, key)
__device__ float g_AO[BSr*DD];             // pre-Wo context [bs][e]
__device__ float g_SF[(size_t)BH*SS_*SS_]; // fallback score buffer

// ---------------- packed f32x2 helpers -------------------------------------
__device__ __forceinline__ void ffma2(unsigned long long& d,
                                      unsigned long long a,
                                      unsigned long long b) {
    asm("fma.rn.f32x2 %0, %1, %2, %0;" : "+l"(d) : "l"(a), "l"(b));
}
__device__ __forceinline__ float f2sum(unsigned long long v) {
    float lo, hi;
    asm("mov.b64 {%0, %1}, %2;" : "=f"(lo), "=f"(hi) : "l"(v));
    return lo + hi;
}
__device__ __forceinline__ float ex2(float x) {
    float r;
    asm("ex2.approx.ftz.f32 %0, %1;" : "=f"(r) : "f"(x));
    return r;
}

// ---------------- K1: fused Q/K/V projection (+mask, +K/V transpose) --------
// grid (BSr/64, 4, 3). C[64 x 64] = A[64 x 128] * W[64 x 128]^T.
// z=0 -> g_Q + maskadd; z=1 -> g_Kp (paired transpose); z=2 -> g_Vt (transpose).
__global__ __launch_bounds__(256, 2)
void gemmQKV(const float* __restrict__ A,
             const float* __restrict__ Wq, const float* __restrict__ Wk,
             const float* __restrict__ Wv)
{
    extern __shared__ float sm[];
    float* Xs  = sm;                // 64*128 = 8192 (reused as Cs 64x65)
    float* Wt2 = sm + 8192;         // 64 j x 65 f2 = 8320 floats

    const int tid = threadIdx.x;
    const int w = tid >> 5, lane = tid & 31;
    const int r0 = w * 8;
    const int row0 = blockIdx.x * 64;
    const int n0 = blockIdx.y * 64;
    const int z = blockIdx.z;
    const float* W = (z == 0) ? Wq : (z == 1) ? Wk : Wv;

    for (int idx = tid; idx < 64 * 128; idx += 256) {
        int r = idx >> 7, d = idx & 127;
        Xs[r * 128 + d] = A[(size_t)(row0 + r) * D0 + d];
    }
    // W pair-interleaved: Wt2[j][e] = (W[e][2j], W[e][2j+1]); lane varies j
#pragma unroll
    for (int t = 0; t < 16; t++) {
        int i = tid + t * 256;              // < 4096
        int j = i & 63, e = i >> 6;
        *reinterpret_cast<unsigned long long*>(&Wt2[(j * 65 + e) * 2]) =
            *reinterpret_cast<const unsigned long long*>(&W[(size_t)(n0 + e) * D0 + 2 * j]);
    }
    __syncthreads();

    unsigned long long acc[8][2];
#pragma unroll
    for (int r = 0; r < 8; r++)
#pragma unroll
        for (int c = 0; c < 2; c++) acc[r][c] = 0ull;

#pragma unroll 8
    for (int j = 0; j < 64; j++) {
        unsigned long long qa[8];
#pragma unroll
        for (int r = 0; r < 8; r++)
            qa[r] = *reinterpret_cast<const unsigned long long*>(
                        &Xs[(r0 + r) * 128 + 2 * j]);
#pragma unroll
        for (int c = 0; c < 2; c++) {
            unsigned long long b2 = *reinterpret_cast<const unsigned long long*>(
                        &Wt2[(j * 65 + lane + 32 * c) * 2]);
#pragma unroll
            for (int r = 0; r < 8; r++) ffma2(acc[r][c], qa[r], b2);
        }
    }

    if (z == 0) {
        int b = row0 >> 10;
#pragma unroll
        for (int r = 0; r < 8; r++) {
            int s = (row0 + r0 + r) & 1023;
#pragma unroll
            for (int c = 0; c < 2; c++) {
                float y = f2sum(acc[r][c]);
                int e = n0 + lane + 32 * c;
                int h = e >> 5, d = e & 31;
                g_Q[(((size_t)(b * HH + h)) * SS_ + s) * HD + d] = y;
                float hs = y;   // head row-sum for mask
#pragma unroll
                for (int off = 16; off; off >>= 1)
                    hs += __shfl_xor_sync(0xffffffffu, hs, off);
                if (lane == 0)
                    g_maskadd[(b * HH + h) * SS_ + s] = (hs != 0.0f) ? 0.0f : -CUDART_INF_F;
            }
        }
    } else {
        __syncthreads();
        float* Cs = Xs;   // 64 x 65
#pragma unroll
        for (int r = 0; r < 8; r++)
#pragma unroll
            for (int c = 0; c < 2; c++)
                Cs[(r0 + r) * 65 + lane + 32 * c] = f2sum(acc[r][c]);
        __syncthreads();
        int b = row0 >> 10;
        if (z == 1) {
            // paired K: g_Kp[(bh*16+j)][s] float2 = (K[2j][s], K[2j+1][s])
#pragma unroll
            for (int t = 0; t < 4; t++) {
                int i = tid + t * 256;          // < 1024
                int pr = i >> 5, sp = i & 31;
                int eL = 2 * pr;
                int e0 = n0 + eL;
                int h = e0 >> 5, j = (e0 & 31) >> 1;
                float4 v = make_float4(Cs[(2 * sp) * 65 + eL],
                                       Cs[(2 * sp) * 65 + eL + 1],
                                       Cs[(2 * sp + 1) * 65 + eL],
                                       Cs[(2 * sp + 1) * 65 + eL + 1]);
                int s0 = (row0 & 1023) + 2 * sp;
                *reinterpret_cast<float4*>(
                    &g_Kp[((((size_t)(b * HH + h)) * 16 + j) * SS_ + s0) * 2]) = v;
            }
        } else {
            // V transposed: g_Vt[bh][d][s]
#pragma unroll
            for (int t = 0; t < 4; t++) {
                int i = tid + t * 256;          // < 1024
                int e = i >> 4, sq = i & 15;
                float4 v = make_float4(Cs[(4 * sq + 0) * 65 + e],
                                       Cs[(4 * sq + 1) * 65 + e],
                                       Cs[(4 * sq + 2) * 65 + e],
                                       Cs[(4 * sq + 3) * 65 + e]);
                int eg = n0 + e;
                int h = eg >> 5, d = eg & 31;
                *reinterpret_cast<float4*>(
                    &g_Vt[(((size_t)(b * HH + h)) * HD + d) * SS_ + (row0 & 1023) + 4 * sq]) = v;
            }
        }
    }
}

// ---------------- K2: output projection  out = g_AO[8192x256] * Wo^T --------
__global__ __launch_bounds__(256, 2)
void gemmO(const float* __restrict__ W, float* __restrict__ Oarg)
{
    extern __shared__ float sm[];
    float* Xs  = sm;                // 64*128
    float* Wt2 = sm + 8192;         // 64 x 65 f2

    const int tid = threadIdx.x;
    const int w = tid >> 5, lane = tid & 31;
    const int r0 = w * 8;
    const int row0 = blockIdx.x * 64;
    const int n0 = blockIdx.y * 64;

    unsigned long long acc[8][2];
#pragma unroll
    for (int r = 0; r < 8; r++)
#pragma unroll
        for (int c = 0; c < 2; c++) acc[r][c] = 0ull;

    for (int k0 = 0; k0 < DD; k0 += 128) {
        __syncthreads();
        for (int idx = tid; idx < 64 * 128; idx += 256) {
            int r = idx >> 7, d = idx & 127;
            Xs[r * 128 + d] = g_AO[(size_t)(row0 + r) * DD + k0 + d];
        }
#pragma unroll
        for (int t = 0; t < 16; t++) {
            int i = tid + t * 256;
            int j = i & 63, e = i >> 6;
            *reinterpret_cast<unsigned long long*>(&Wt2[(j * 65 + e) * 2]) =
                *reinterpret_cast<const unsigned long long*>(
                    &W[(size_t)(n0 + e) * DD + k0 + 2 * j]);
        }
        __syncthreads();
#pragma unroll 8
        for (int j = 0; j < 64; j++) {
            unsigned long long qa[8];
#pragma unroll
            for (int r = 0; r < 8; r++)
                qa[r] = *reinterpret_cast<const unsigned long long*>(
                            &Xs[(r0 + r) * 128 + 2 * j]);
#pragma unroll
            for (int c = 0; c < 2; c++) {
                unsigned long long b2 = *reinterpret_cast<const unsigned long long*>(
                            &Wt2[(j * 65 + lane + 32 * c) * 2]);
#pragma unroll
                for (int r = 0; r < 8; r++) ffma2(acc[r][c], qa[r], b2);
            }
        }
    }
#pragma unroll
    for (int r = 0; r < 8; r++)
#pragma unroll
        for (int c = 0; c < 2; c++)
            Oarg[(size_t)(row0 + r0 + r) * D0 + n0 + lane + 32 * c] = f2sum(acc[r][c]);
}

// ---------------- K3: fused attention ---------------------------------------
// grid (S/64, BH), 256 thr, 2 CTAs/SM. Warp w owns rows 8w..8w+7.
__global__ __launch_bounds__(256, 2)
void attn_kernel(const float* __restrict__ U, float* __restrict__ sattn)
{
    extern __shared__ float sm[];
    float* Qs    = sm;              // 64*32  = 2048
    float* msk   = sm + 2048;       // 1024
    float* inv_s = sm + 3072;       // 64 (+pad)
    float* KVt   = sm + 3152;       // K: 16x130 f2 = 4160 | V: 32x130 = 4160
    float* Ps    = sm + 3152 + 4160;// 64*132 = 8448
    // total 15760 floats = 63040 B

    const int tid = threadIdx.x, w = tid >> 5, lane = tid & 31;
    const int r0 = w * 8;
    const int bh = blockIdx.y;
    const int q0 = blockIdx.x * 64;
    const float inv_scale = 0.17677669529663687f;   // 1/sqrt(32)

    const float* gq  = g_Q  + (size_t)bh * SS_ * HD;
    const float* gkp = g_Kp + (size_t)bh * HD * SS_;   // 16 pair-rows x S f2
    const float* gvt = g_Vt + (size_t)bh * HD * SS_;
    float* srow = sattn + ((size_t)bh * SS_ + q0) * SS_;

    {   // stage Q tile (64x32) + mask
        const float4* q4 = reinterpret_cast<const float4*>(gq + (size_t)q0 * HD);
        reinterpret_cast<float4*>(Qs)[tid]       = q4[tid];
        reinterpret_cast<float4*>(Qs)[tid + 256] = q4[tid + 256];
        const float4* m4 = reinterpret_cast<const float4*>(g_maskadd + bh * SS_);
        reinterpret_cast<float4*>(msk)[tid] = m4[tid];
    }

    float l_loc[8];
#pragma unroll
    for (int r = 0; r < 8; r++) l_loc[r] = 0.f;

    // ---- phase 1: QK -> e = exp(score) -> gmem; l += e ----
    for (int kb = 0; kb < SS_; kb += 128) {
        __syncthreads();
        {   // stage paired K tile [j][k] f2, pad 130 f2 (even -> 16B rows)
#pragma unroll
            for (int t = 0; t < 4; t++) {
                int i = tid + t * 256;      // < 1024
                int j = i >> 6, kq = i & 63;
                float4 v = *reinterpret_cast<const float4*>(
                               &gkp[((size_t)j * SS_ + kb + 2 * kq) * 2]);
                *reinterpret_cast<float4*>(&KVt[(j * 130 + 2 * kq) * 2]) = v;
            }
        }
        __syncthreads();

        unsigned long long acc[8][4];
#pragma unroll
        for (int r = 0; r < 8; r++)
#pragma unroll
            for (int c = 0; c < 4; c++) acc[r][c] = 0ull;

#pragma unroll
        for (int j = 0; j < HD / 2; j++) {
            unsigned long long qa[8];
#pragma unroll
            for (int r = 0; r < 8; r++)
                qa[r] = *reinterpret_cast<const unsigned long long*>(
                            &Qs[(r0 + r) * HD + 2 * j]);
#pragma unroll
            for (int c = 0; c < 4; c++) {
                unsigned long long b2 = *reinterpret_cast<const unsigned long long*>(
                            &KVt[(j * 130 + lane + 32 * c) * 2]);
#pragma unroll
                for (int r = 0; r < 8; r++) ffma2(acc[r][c], qa[r], b2);
            }
        }

#pragma unroll
        for (int r = 0; r < 8; r++) {
            const float* up = U + ((size_t)bh * SS_ + q0 + r0 + r) * SS_ + kb + lane;
            float* ep = srow + (size_t)(r0 + r) * SS_ + kb + lane;
            float lr = l_loc[r];
#pragma unroll
            for (int c = 0; c < 4; c++) {
                float s = (f2sum(acc[r][c]) + up[32 * c]) * inv_scale
                        + msk[kb + lane + 32 * c];
                float e = ex2(s * LOG2E);   // exp(s); -inf -> 0
                ep[32 * c] = e;
                lr += e;
            }
            l_loc[r] = lr;
        }
    }

    // ---- phase 2: warp-sum l -> inv ----
#pragma unroll
    for (int r = 0; r < 8; r++) {
        float l = l_loc[r];
#pragma unroll
        for (int off = 16; off; off >>= 1)
            l += __shfl_xor_sync(0xffffffffu, l, off);
        if (lane == 0) inv_s[r0 + r] = 1.0f / l;
    }

    // ---- phase 3: normalize + write attn + AV ----
    unsigned long long oacc[8];
#pragma unroll
    for (int r = 0; r < 8; r++) oacc[r] = 0ull;

    for (int vb = 0; vb < SS_; vb += 128) {
        __syncthreads();    // inv visible (1st iter); KVt/Ps reuse-safe after
        {   // stage V tile [d][k] pad 130 (STS.64 pair)
#pragma unroll
            for (int t = 0; t < 4; t++) {
                int i = tid + t * 256;
                int d = i >> 5, kq = i & 31;
                float4 v = *reinterpret_cast<const float4*>(
                               &gvt[(size_t)d * SS_ + vb + 4 * kq]);
                float* dst = &KVt[d * 130 + 4 * kq];
                *reinterpret_cast<float2*>(dst)     = make_float2(v.x, v.y);
                *reinterpret_cast<float2*>(dst + 2) = make_float2(v.z, v.w);
            }
        }
        {   // P tile: p = e * inv -> final attn + Ps
#pragma unroll
            for (int t = 0; t < 8; t++) {
                int i = tid + t * 256;      // < 2048
                int row = i >> 5, q4 = i & 31;
                float iv = inv_s[row];
                float4* ep4 = reinterpret_cast<float4*>(
                                  srow + (size_t)row * SS_ + vb + 4 * q4);
                float4 v = *ep4;
                v.x *= iv; v.y *= iv; v.z *= iv; v.w *= iv;
                *ep4 = v;
                *reinterpret_cast<float4*>(&Ps[row * 132 + 4 * q4]) = v;
            }
        }
        __syncthreads();
        // AV: lane = head dim d; all operands direct LDS.64
#pragma unroll 4
        for (int k = 0; k < 128; k += 4) {
            unsigned long long v2a = *reinterpret_cast<const unsigned long long*>(
                    &KVt[lane * 130 + k]);
            unsigned long long v2b = *reinterpret_cast<const unsigned long long*>(
                    &KVt[lane * 130 + k + 2]);
#pragma unroll
            for (int r = 0; r < 8; r++) {
                unsigned long long pa = *reinterpret_cast<const unsigned long long*>(
                        &Ps[(r0 + r) * 132 + k]);
                unsigned long long pb = *reinterpret_cast<const unsigned long long*>(
                        &Ps[(r0 + r) * 132 + k + 2]);
                ffma2(oacc[r], pa, v2a);
                ffma2(oacc[r], pb, v2b);
            }
        }
    }

    {
        int b = bh >> 3, h = bh & 7;
#pragma unroll
        for (int r = 0; r < 8; r++) {
            int s = q0 + r0 + r;
            g_AO[((size_t)b * SS_ + s) * DD + h * HD + lane] = f2sum(oacc[r]);
        }
    }
}

// ---------------- launcher --------------------------------------------------
extern "C" void kernel_launch(void* const* d_in, const int* in_sizes, int n_in,
                              void* d_out, int out_size)
{
    const float* query = (const float*)d_in[0];
    const float* U     = (const float*)d_in[1];
    const float* Wq    = (const float*)d_in[2];
    const float* Wk    = (const float*)d_in[3];
    const float* Wv    = (const float*)d_in[4];
    const float* Wo    = (const float*)d_in[5];

    float* outp = (float*)d_out;
    const long long total = (long long)BSr * D0 + (long long)BH * SS_ * SS_;
    float* attnp = nullptr;
    if ((long long)out_size >= total) attnp = outp + (size_t)BSr * D0;

    float* sbuf = attnp;
    if (!sbuf) { cudaGetSymbolAddress((void**)&sbuf, g_SF); }

    const size_t gemm_smem = (size_t)(8192 + 8320) * sizeof(float);   // 66048 B
    const size_t attn_smem = (size_t)15760 * sizeof(float);           // 63040 B
    cudaFuncSetAttribute(gemmQKV, cudaFuncAttributeMaxDynamicSharedMemorySize, (int)gemm_smem);
    cudaFuncSetAttribute(gemmO, cudaFuncAttributeMaxDynamicSharedMemorySize, (int)gemm_smem);
    cudaFuncSetAttribute(attn_kernel, cudaFuncAttributeMaxDynamicSharedMemorySize, (int)attn_smem);

    // Q/K/V projections (+mask, +K paired / V transposed)
    gemmQKV<<<dim3(BSr / 64, 4, 3), 256, gemm_smem>>>(query, Wq, Wk, Wv);

    // attention
    attn_kernel<<<dim3(SS_ / 64, BH), 256, attn_smem>>>(U, sbuf);

    // output projection
    gemmO<<<dim3(BSr / 64, 2), 256, gemm_smem>>>(Wo, outp);
}